// round 15
// baseline (speedup 1.0000x reference)
#include <cuda_runtime.h>
#include <cuda_fp16.h>
#include <math.h>
#include <stdint.h>

// ---------------- problem constants ----------------
#define BB   16384
#define DIM  1024
#define HH   16
#define HD   64
#define FFN  4096
#define LNEPS 1e-5f

#define BD   ((size_t)BB * DIM)
#define BF   ((size_t)BB * FFN)
#define WSZ  (1024*1024)

// ---------------- scratch ----------------
__device__ __half g_mods[3 * BD];
__device__ __half g_mean[BD];
__device__ __half g_qin [BD];
__device__ __half g_x   [BD];
__device__ __half g_h   [BF];
__device__ __half g_q   [BD];
__device__ __half g_K   [3 * BD];
__device__ __half g_V   [3 * BD];
__device__ __half g_w   [4 * WSZ + 2 * (size_t)DIM * FFN];
__device__ float  g_y   [BD];

// ---------------- prep kernels ----------------
__global__ void prep_mods_k(const float4* __restrict__ a, const float4* __restrict__ b,
                            const float4* __restrict__ c,
                            __half2* __restrict__ o0, __half2* __restrict__ o1,
                            __half2* __restrict__ o2, __half2* __restrict__ om, int n4) {
    int i = blockIdx.x * blockDim.x + threadIdx.x;
    int st = gridDim.x * blockDim.x;
    const float third = 1.f / 3.f;
    for (; i < n4; i += st) {
        float4 x = a[i], y = b[i], z = c[i];
        o0[2*i]   = __floats2half2_rn(x.x, x.y);
        o0[2*i+1] = __floats2half2_rn(x.z, x.w);
        o1[2*i]   = __floats2half2_rn(y.x, y.y);
        o1[2*i+1] = __floats2half2_rn(y.z, y.w);
        o2[2*i]   = __floats2half2_rn(z.x, z.y);
        o2[2*i+1] = __floats2half2_rn(z.z, z.w);
        om[2*i]   = __floats2half2_rn((x.x + y.x + z.x) * third, (x.y + y.y + z.y) * third);
        om[2*i+1] = __floats2half2_rn((x.z + y.z + z.z) * third, (x.w + y.w + z.w) * third);
    }
}
// Batched transpose: z selects among up to 4 DIMxDIM weights.
__global__ void transpose4_half_k(const float* __restrict__ Wa, const float* __restrict__ Wb,
                                  const float* __restrict__ Wc, const float* __restrict__ Wd,
                                  __half* __restrict__ Ta, __half* __restrict__ Tb,
                                  __half* __restrict__ Tc, __half* __restrict__ Td) {
    __shared__ float t[32][33];
    const float* W = (blockIdx.z == 0) ? Wa : (blockIdx.z == 1) ? Wb
                   : (blockIdx.z == 2) ? Wc : Wd;
    __half* Wt = (blockIdx.z == 0) ? Ta : (blockIdx.z == 1) ? Tb
               : (blockIdx.z == 2) ? Tc : Td;
    int nb = blockIdx.x * 32, kb = blockIdx.y * 32;
    int tx = threadIdx.x, ty = threadIdx.y;
    #pragma unroll
    for (int r = 0; r < 32; r += 8)
        t[ty + r][tx] = W[(size_t)(kb + ty + r) * DIM + nb + tx];
    __syncthreads();
    #pragma unroll
    for (int r = 0; r < 32; r += 8)
        Wt[(size_t)(nb + ty + r) * DIM + kb + tx] = __float2half(t[tx][ty + r]);
}
// Generic single transpose (for W1, W2)
__global__ void transpose_half_k(const float* __restrict__ W, __half* __restrict__ Wt,
                                 int K, int N) {
    __shared__ float t[32][33];
    int nb = blockIdx.x * 32, kb = blockIdx.y * 32;
    int tx = threadIdx.x, ty = threadIdx.y;
    #pragma unroll
    for (int r = 0; r < 32; r += 8)
        t[ty + r][tx] = W[(size_t)(kb + ty + r) * N + nb + tx];
    __syncthreads();
    #pragma unroll
    for (int r = 0; r < 32; r += 8)
        Wt[(size_t)(nb + ty + r) * K + kb + tx] = __float2half(t[tx][ty + r]);
}

// ---------------- shared GEMM bits ----------------
__device__ __forceinline__ void ldsm4(uint32_t* r, uint32_t addr) {
    asm volatile("ldmatrix.sync.aligned.m8n8.x4.shared.b16 {%0,%1,%2,%3}, [%4];"
                 : "=r"(r[0]), "=r"(r[1]), "=r"(r[2]), "=r"(r[3]) : "r"(addr));
}

// ---------------- big-tile GEMM: 128x128x64, 4 warps, warp tile 64x64 -----------
#define BM 128
#define BN 128
#define BK 64
#define NSTG 3
#define NTHR 128
#define ASTR 72
#define BSTR 72
#define A_ELEMS (BM * ASTR)          // 9216 halves / stage
#define B_ELEMS (BN * BSTR)
#define GSMEM (NSTG * (A_ELEMS + B_ELEMS) * 2)   // 110592 B -> 2 CTA/SM

// MODE: 0 = +bias; 2 = relu(+bias);
// MODE 3 = merged K/V batch: z in [0,6): A = A0 + (z%3)*BD; K-half (z<3) or V-half.
template <int MODE, typename OutT>
__global__ __launch_bounds__(NTHR, 2) void gemm_fp16(
    const __half* __restrict__ A0, const __half* __restrict__ A1, const __half* __restrict__ A2,
    const __half* __restrict__ Wt, const __half* __restrict__ Wt2,
    const float* __restrict__ bias, const float* __restrict__ bias2,
    const float* __restrict__ addsrc,
    OutT* __restrict__ C0, OutT* __restrict__ C1, OutT* __restrict__ C2,
    int K, int Nc)
{
    extern __shared__ __align__(16) __half smh[];
    __half* As = smh;
    __half* Bs = smh + NSTG * A_ELEMS;

    const __half* A;
    const __half* W;
    const float*  bvec;
    OutT*         C;
    if (MODE == 3) {
        int z = blockIdx.z;
        A    = A0 + (size_t)(z % 3) * BD;
        W    = (z < 3) ? Wt : Wt2;
        bvec = (z < 3) ? bias : bias2;
        C    = (z < 3) ? (C0 + (size_t)z * BD) : (C1 + (size_t)(z - 3) * BD);
    } else {
        A    = (blockIdx.z == 0) ? A0 : (blockIdx.z == 1) ? A1 : A2;
        W    = Wt;
        bvec = bias;
        C    = (blockIdx.z == 0) ? C0 : (blockIdx.z == 1) ? C1 : C2;
    }

    const int m0 = blockIdx.y * BM, n0 = blockIdx.x * BN;
    const int tid  = threadIdx.x;
    const int lane = tid & 31, warp = tid >> 5;
    const int wm = warp & 1, wn = warp >> 1;          // 2m x 2n, warp tile 64x64
    const int g = lane >> 2, tig = lane & 3;

    const uint32_t sm_a = (uint32_t)__cvta_generic_to_shared(As);
    const uint32_t sm_b = (uint32_t)__cvta_generic_to_shared(Bs);

    const int a_off = (wm * 64 + (lane & 15)) * ASTR + (lane >> 4) * 8;
    const int b_off = (wn * 64 + (lane & 7) + ((lane >= 16) ? 8 : 0)) * BSTR
                    + ((lane >> 3) & 1) * 8;

    auto load_stage = [&](int stage, int kb) {
        const __half* Ag = A + (size_t)m0 * K + kb;
        #pragma unroll
        for (int p = 0; p < 8; p++) {
            int cidx = tid + p * NTHR;
            int m = cidx >> 3, sg = cidx & 7;
            uint32_t dst = sm_a + (uint32_t)(stage * A_ELEMS + m * ASTR + sg * 8) * 2;
            const __half* src = Ag + (size_t)m * K + sg * 8;
            asm volatile("cp.async.cg.shared.global [%0], [%1], 16;\n" :: "r"(dst), "l"(src));
        }
        const __half* Bg = W + (size_t)n0 * K + kb;
        #pragma unroll
        for (int p = 0; p < 8; p++) {
            int cidx = tid + p * NTHR;
            int n = cidx >> 3, sg = cidx & 7;
            uint32_t dst = sm_b + (uint32_t)(stage * B_ELEMS + n * BSTR + sg * 8) * 2;
            const __half* src = Bg + (size_t)n * K + sg * 8;
            asm volatile("cp.async.cg.shared.global [%0], [%1], 16;\n" :: "r"(dst), "l"(src));
        }
        asm volatile("cp.async.commit_group;\n");
    };

    float c[4][8][4];
    #pragma unroll
    for (int i = 0; i < 4; i++)
        #pragma unroll
        for (int j = 0; j < 8; j++)
            #pragma unroll
            for (int l = 0; l < 4; l++) c[i][j][l] = 0.f;

    load_stage(0, 0);
    load_stage(1, BK);

    uint32_t af[2][4][4], bf[2][8][2];

    const int KT = K / BK;
    for (int kt = 0; kt < KT; ++kt) {
        if (kt + 1 < KT) asm volatile("cp.async.wait_group 1;\n");
        else             asm volatile("cp.async.wait_group 0;\n");
        __syncthreads();

        if (kt + 2 < KT) load_stage((kt + 2) % NSTG, (kt + 2) * BK);

        const int cur = kt % NSTG;
        const uint32_t abase = sm_a + (uint32_t)(cur * A_ELEMS + a_off) * 2;
        const uint32_t bbase = sm_b + (uint32_t)(cur * B_ELEMS + b_off) * 2;

        #pragma unroll
        for (int mi = 0; mi < 4; mi++)
            ldsm4(af[0][mi], abase + (uint32_t)(mi * 16 * ASTR) * 2);
        #pragma unroll
        for (int nip = 0; nip < 4; nip++) {
            uint32_t r[4];
            ldsm4(r, bbase + (uint32_t)(nip * 16 * BSTR) * 2);
            bf[0][2 * nip][0]     = r[0];
            bf[0][2 * nip][1]     = r[1];
            bf[0][2 * nip + 1][0] = r[2];
            bf[0][2 * nip + 1][1] = r[3];
        }

        #pragma unroll
        for (int ks = 0; ks < 4; ++ks) {
            const int cb = ks & 1;
            if (ks < 3) {
                const int nb = cb ^ 1;
                const int kk = (ks + 1) * 16;
                #pragma unroll
                for (int mi = 0; mi < 4; mi++)
                    ldsm4(af[nb][mi], abase + (uint32_t)(mi * 16 * ASTR + kk) * 2);
                #pragma unroll
                for (int nip = 0; nip < 4; nip++) {
                    uint32_t r[4];
                    ldsm4(r, bbase + (uint32_t)(nip * 16 * BSTR + kk) * 2);
                    bf[nb][2 * nip][0]     = r[0];
                    bf[nb][2 * nip][1]     = r[1];
                    bf[nb][2 * nip + 1][0] = r[2];
                    bf[nb][2 * nip + 1][1] = r[3];
                }
            }
            #pragma unroll
            for (int mi = 0; mi < 4; mi++)
                #pragma unroll
                for (int ni = 0; ni < 8; ni++) {
                    float* cc = c[mi][ni];
                    asm volatile(
                        "mma.sync.aligned.m16n8k16.row.col.f32.f16.f16.f32 "
                        "{%0,%1,%2,%3},{%4,%5,%6,%7},{%8,%9},{%0,%1,%2,%3};\n"
                        : "+f"(cc[0]), "+f"(cc[1]), "+f"(cc[2]), "+f"(cc[3])
                        : "r"(af[cb][mi][0]), "r"(af[cb][mi][1]),
                          "r"(af[cb][mi][2]), "r"(af[cb][mi][3]),
                          "r"(bf[cb][ni][0]), "r"(bf[cb][ni][1]));
                }
        }
    }

    // epilogue
    #pragma unroll
    for (int mi = 0; mi < 4; mi++) {
        int row = m0 + wm * 64 + mi * 16 + g;
        #pragma unroll
        for (int ni = 0; ni < 8; ni++) {
            int col = n0 + wn * 64 + ni * 8 + tig * 2;
            float bv0 = bvec[col], bv1 = bvec[col + 1];
            float v0 = c[mi][ni][0] + bv0, v1 = c[mi][ni][1] + bv1;
            float v2 = c[mi][ni][2] + bv0, v3 = c[mi][ni][3] + bv1;
            size_t i0 = (size_t)row * Nc + col;
            size_t i1 = (size_t)(row + 8) * Nc + col;
            if (MODE == 2) {
                v0 = fmaxf(v0, 0.f); v1 = fmaxf(v1, 0.f);
                v2 = fmaxf(v2, 0.f); v3 = fmaxf(v3, 0.f);
            }
            if (sizeof(OutT) == 2) {
                *(__half2*)&((__half*)C)[i0] = __floats2half2_rn(v0, v1);
                *(__half2*)&((__half*)C)[i1] = __floats2half2_rn(v2, v3);
            } else {
                *(float2*)&((float*)C)[i0] = make_float2(v0, v1);
                *(float2*)&((float*)C)[i1] = make_float2(v2, v3);
            }
        }
    }
}

// ---------------- small-tile GEMM: 64x128x64, 4 warps, warp tile 32x64 ----------
// For the N=1024 GEMMs (qin, q, W2): 2048 CTAs -> 6.9 waves, ~1% tail.
#define SBM 64
#define SA_ELEMS (SBM * ASTR)        // 4608 halves / stage
#define SGSMEM (NSTG * (SA_ELEMS + B_ELEMS) * 2)   // 82944 B -> 2 CTA/SM

// MODE: 0 = +bias; 1 = +bias+addsrc
template <int MODE, typename OutT>
__global__ __launch_bounds__(NTHR, 2) void gemm_fp16_sm(
    const __half* __restrict__ A0, const __half* __restrict__ Wt,
    const float* __restrict__ bias, const float* __restrict__ addsrc,
    OutT* __restrict__ C0, int K, int Nc)
{
    extern __shared__ __align__(16) __half smh[];
    __half* As = smh;
    __half* Bs = smh + NSTG * SA_ELEMS;

    const __half* A = A0;
    OutT*         C = C0;

    const int m0 = blockIdx.y * SBM, n0 = blockIdx.x * BN;
    const int tid  = threadIdx.x;
    const int lane = tid & 31, warp = tid >> 5;
    const int wm = warp & 1, wn = warp >> 1;          // 2m x 2n, warp tile 32x64
    const int g = lane >> 2, tig = lane & 3;

    const uint32_t sm_a = (uint32_t)__cvta_generic_to_shared(As);
    const uint32_t sm_b = (uint32_t)__cvta_generic_to_shared(Bs);

    const int a_off = (wm * 32 + (lane & 15)) * ASTR + (lane >> 4) * 8;
    const int b_off = (wn * 64 + (lane & 7) + ((lane >= 16) ? 8 : 0)) * BSTR
                    + ((lane >> 3) & 1) * 8;

    auto load_stage = [&](int stage, int kb) {
        const __half* Ag = A + (size_t)m0 * K + kb;
        #pragma unroll
        for (int p = 0; p < 4; p++) {                 // 64 rows x 8 segs = 512 chunks
            int cidx = tid + p * NTHR;
            int m = cidx >> 3, sg = cidx & 7;
            uint32_t dst = sm_a + (uint32_t)(stage * SA_ELEMS + m * ASTR + sg * 8) * 2;
            const __half* src = Ag + (size_t)m * K + sg * 8;
            asm volatile("cp.async.cg.shared.global [%0], [%1], 16;\n" :: "r"(dst), "l"(src));
        }
        const __half* Bg = Wt + (size_t)n0 * K + kb;
        #pragma unroll
        for (int p = 0; p < 8; p++) {                 // 128 rows x 8 segs = 1024 chunks
            int cidx = tid + p * NTHR;
            int n = cidx >> 3, sg = cidx & 7;
            uint32_t dst = sm_b + (uint32_t)(stage * B_ELEMS + n * BSTR + sg * 8) * 2;
            const __half* src = Bg + (size_t)n * K + sg * 8;
            asm volatile("cp.async.cg.shared.global [%0], [%1], 16;\n" :: "r"(dst), "l"(src));
        }
        asm volatile("cp.async.commit_group;\n");
    };

    float c[2][8][4];
    #pragma unroll
    for (int i = 0; i < 2; i++)
        #pragma unroll
        for (int j = 0; j < 8; j++)
            #pragma unroll
            for (int l = 0; l < 4; l++) c[i][j][l] = 0.f;

    load_stage(0, 0);
    load_stage(1, BK);

    const int KT = K / BK;
    for (int kt = 0; kt < KT; ++kt) {
        if (kt + 1 < KT) asm volatile("cp.async.wait_group 1;\n");
        else             asm volatile("cp.async.wait_group 0;\n");
        __syncthreads();

        if (kt + 2 < KT) load_stage((kt + 2) % NSTG, (kt + 2) * BK);

        const int cur = kt % NSTG;
        const uint32_t abase = sm_a + (uint32_t)(cur * SA_ELEMS + a_off) * 2;
        const uint32_t bbase = sm_b + (uint32_t)(cur * B_ELEMS + b_off) * 2;

        #pragma unroll
        for (int ks = 0; ks < 4; ++ks) {
            const int kk = ks * 16;
            uint32_t a[2][4], b[8][2];
            #pragma unroll
            for (int mi = 0; mi < 2; mi++)
                ldsm4(a[mi], abase + (uint32_t)(mi * 16 * ASTR + kk) * 2);
            #pragma unroll
            for (int nip = 0; nip < 4; nip++) {
                uint32_t r[4];
                ldsm4(r, bbase + (uint32_t)(nip * 16 * BSTR + kk) * 2);
                b[2 * nip][0]     = r[0];
                b[2 * nip][1]     = r[1];
                b[2 * nip + 1][0] = r[2];
                b[2 * nip + 1][1] = r[3];
            }
            #pragma unroll
            for (int mi = 0; mi < 2; mi++)
                #pragma unroll
                for (int ni = 0; ni < 8; ni++) {
                    float* cc = c[mi][ni];
                    asm volatile(
                        "mma.sync.aligned.m16n8k16.row.col.f32.f16.f16.f32 "
                        "{%0,%1,%2,%3},{%4,%5,%6,%7},{%8,%9},{%0,%1,%2,%3};\n"
                        : "+f"(cc[0]), "+f"(cc[1]), "+f"(cc[2]), "+f"(cc[3])
                        : "r"(a[mi][0]), "r"(a[mi][1]), "r"(a[mi][2]), "r"(a[mi][3]),
                          "r"(b[ni][0]), "r"(b[ni][1]));
                }
        }
    }

    // epilogue
    #pragma unroll
    for (int mi = 0; mi < 2; mi++) {
        int row = m0 + wm * 32 + mi * 16 + g;
        #pragma unroll
        for (int ni = 0; ni < 8; ni++) {
            int col = n0 + wn * 64 + ni * 8 + tig * 2;
            float bv0 = bias[col], bv1 = bias[col + 1];
            float v0 = c[mi][ni][0] + bv0, v1 = c[mi][ni][1] + bv1;
            float v2 = c[mi][ni][2] + bv0, v3 = c[mi][ni][3] + bv1;
            size_t i0 = (size_t)row * Nc + col;
            size_t i1 = (size_t)(row + 8) * Nc + col;
            if (MODE == 1) {
                v0 += addsrc[i0]; v1 += addsrc[i0 + 1];
                v2 += addsrc[i1]; v3 += addsrc[i1 + 1];
            }
            if (sizeof(OutT) == 2) {
                *(__half2*)&((__half*)C)[i0] = __floats2half2_rn(v0, v1);
                *(__half2*)&((__half*)C)[i1] = __floats2half2_rn(v2, v3);
            } else {
                *(float2*)&((float*)C)[i0] = make_float2(v0, v1);
                *(float2*)&((float*)C)[i1] = make_float2(v2, v3);
            }
        }
    }
}

// ---------------- attention (3 keys) + residual + LN1, fp16 q/K/V ----------------
__global__ __launch_bounds__(512) void attn_ln1_k(
    const __half* __restrict__ q,
    const __half* __restrict__ K0, const __half* __restrict__ K1, const __half* __restrict__ K2,
    const __half* __restrict__ V0, const __half* __restrict__ V1, const __half* __restrict__ V2,
    const float* __restrict__ dom, const float* __restrict__ gam, const float* __restrict__ bet,
    __half* __restrict__ xo)
{
    __shared__ float sout[DIM];
    __shared__ float rS[16], rQ[16], stats[2];
    const int b = blockIdx.x, tid = threadIdx.x;
    const int h = tid >> 5, lane = tid & 31;
    const size_t rowb = (size_t)b * DIM;
    const size_t off = rowb + h * HD + lane * 2;

    float2 qv = __half22float2(*(const __half2*)(q + off));
    float2 k0 = __half22float2(*(const __half2*)(K0 + off));
    float2 k1 = __half22float2(*(const __half2*)(K1 + off));
    float2 k2 = __half22float2(*(const __half2*)(K2 + off));
    float d0 = qv.x * k0.x + qv.y * k0.y;
    float d1 = qv.x * k1.x + qv.y * k1.y;
    float d2 = qv.x * k2.x + qv.y * k2.y;
    #pragma unroll
    for (int o = 16; o; o >>= 1) {
        d0 += __shfl_xor_sync(0xffffffffu, d0, o);
        d1 += __shfl_xor_sync(0xffffffffu, d1, o);
        d2 += __shfl_xor_sync(0xffffffffu, d2, o);
    }
    float s0 = d0 * 0.125f, s1 = d1 * 0.125f, s2 = d2 * 0.125f;
    float mx = fmaxf(s0, fmaxf(s1, s2));
    float e0 = expf(s0 - mx), e1 = expf(s1 - mx), e2 = expf(s2 - mx);
    float inv = 1.f / (e0 + e1 + e2);
    float p0 = e0 * inv, p1 = e1 * inv, p2 = e2 * inv;

    float2 v0 = __half22float2(*(const __half2*)(V0 + off));
    float2 v1 = __half22float2(*(const __half2*)(V1 + off));
    float2 v2 = __half22float2(*(const __half2*)(V2 + off));
    float ox = p0 * v0.x + p1 * v1.x + p2 * v2.x;
    float oy = p0 * v0.y + p1 * v1.y + p2 * v2.y;
    int dloc = h * HD + lane * 2;
    sout[dloc] = ox;
    sout[dloc + 1] = oy;
    __syncthreads();

    int d0i = tid * 2;
    float t0 = dom[rowb + d0i]     + sout[d0i];
    float t1 = dom[rowb + d0i + 1] + sout[d0i + 1];
    float s = t0 + t1, sq = t0 * t0 + t1 * t1;
    #pragma unroll
    for (int o = 16; o; o >>= 1) {
        s  += __shfl_xor_sync(0xffffffffu, s, o);
        sq += __shfl_xor_sync(0xffffffffu, sq, o);
    }
    if (lane == 0) { rS[h] = s; rQ[h] = sq; }
    __syncthreads();
    if (tid == 0) {
        float S = 0.f, Q = 0.f;
        #pragma unroll
        for (int i = 0; i < 16; i++) { S += rS[i]; Q += rQ[i]; }
        float mu = S * (1.f / DIM);
        float var = Q * (1.f / DIM) - mu * mu;
        stats[0] = mu;
        stats[1] = rsqrtf(var + LNEPS);
    }
    __syncthreads();
    float mu = stats[0], r = stats[1];
    float x0 = (t0 - mu) * r * gam[d0i]     + bet[d0i];
    float x1 = (t1 - mu) * r * gam[d0i + 1] + bet[d0i + 1];
    *(__half2*)(xo + rowb + d0i) = __floats2half2_rn(x0, x1);
}

// ---------------- residual + LN2 + [DIM,3] matvec + softmax ----------------
__global__ __launch_bounds__(256) void final_k(
    const __half* __restrict__ x, const float* __restrict__ y,
    const float* __restrict__ g2, const float* __restrict__ b2,
    const float* __restrict__ Ww, const float* __restrict__ bw,
    float* __restrict__ out)
{
    __shared__ float rs[8], rq[8], rl[8][3], stats[2];
    const int b = blockIdx.x, tid = threadIdx.x;
    const int lane = tid & 31, w = tid >> 5;
    const size_t base = (size_t)b * DIM;

    float t[4];
    float s = 0.f, sq = 0.f;
    #pragma unroll
    for (int i = 0; i < 4; i++) {
        int d = tid + i * 256;
        float v = __half2float(x[base + d]) + y[base + d];
        t[i] = v; s += v; sq += v * v;
    }
    #pragma unroll
    for (int o = 16; o; o >>= 1) {
        s  += __shfl_xor_sync(0xffffffffu, s, o);
        sq += __shfl_xor_sync(0xffffffffu, sq, o);
    }
    if (lane == 0) { rs[w] = s; rq[w] = sq; }
    __syncthreads();
    if (tid == 0) {
        float S = 0.f, Q = 0.f;
        #pragma unroll
        for (int i = 0; i < 8; i++) { S += rs[i]; Q += rq[i]; }
        float mu = S * (1.f / DIM);
        float var = Q * (1.f / DIM) - mu * mu;
        stats[0] = mu;
        stats[1] = rsqrtf(var + LNEPS);
    }
    __syncthreads();
    float mu = stats[0], r = stats[1];
    float l0 = 0.f, l1 = 0.f, l2 = 0.f;
    #pragma unroll
    for (int i = 0; i < 4; i++) {
        int d = tid + i * 256;
        float xn = (t[i] - mu) * r * g2[d] + b2[d];
        l0 += xn * Ww[d * 3];
        l1 += xn * Ww[d * 3 + 1];
        l2 += xn * Ww[d * 3 + 2];
    }
    #pragma unroll
    for (int o = 16; o; o >>= 1) {
        l0 += __shfl_xor_sync(0xffffffffu, l0, o);
        l1 += __shfl_xor_sync(0xffffffffu, l1, o);
        l2 += __shfl_xor_sync(0xffffffffu, l2, o);
    }
    if (lane == 0) { rl[w][0] = l0; rl[w][1] = l1; rl[w][2] = l2; }
    __syncthreads();
    if (tid == 0) {
        float a0 = bw[0], a1 = bw[1], a2 = bw[2];
        #pragma unroll
        for (int i = 0; i < 8; i++) { a0 += rl[i][0]; a1 += rl[i][1]; a2 += rl[i][2]; }
        float m = fmaxf(a0, fmaxf(a1, a2));
        float e0 = expf(a0 - m), e1 = expf(a1 - m), e2 = expf(a2 - m);
        float inv = 1.f / (e0 + e1 + e2);
        out[(size_t)b * 3]     = e0 * inv;
        out[(size_t)b * 3 + 1] = e1 * inv;
        out[(size_t)b * 3 + 2] = e2 * inv;
    }
}

// ---------------- host launcher ----------------
extern "C" void kernel_launch(void* const* d_in, const int* in_sizes, int n_in,
                              void* d_out, int out_size)
{
    (void)in_sizes; (void)n_in; (void)out_size;
    const float* m0  = (const float*)d_in[0];
    const float* m1  = (const float*)d_in[1];
    const float* m2  = (const float*)d_in[2];
    const float* dom = (const float*)d_in[3];
    const float* Wg  = (const float*)d_in[4];
    const float* bg  = (const float*)d_in[5];
    const float* Wq  = (const float*)d_in[6];
    const float* bq  = (const float*)d_in[7];
    const float* Wk  = (const float*)d_in[8];
    const float* bk  = (const float*)d_in[9];
    const float* Wv  = (const float*)d_in[10];
    const float* bv  = (const float*)d_in[11];
    const float* W1  = (const float*)d_in[12];
    const float* b1  = (const float*)d_in[13];
    const float* W2  = (const float*)d_in[14];
    const float* b2  = (const float*)d_in[15];
    const float* g1  = (const float*)d_in[16];
    const float* be1 = (const float*)d_in[17];
    const float* g2  = (const float*)d_in[18];
    const float* be2 = (const float*)d_in[19];
    const float* Ww  = (const float*)d_in[20];
    const float* bw  = (const float*)d_in[21];
    float* out = (float*)d_out;

    __half *pmods, *pmean, *pqin, *px, *ph, *pw, *pq, *pK, *pV;
    float  *py;
    cudaGetSymbolAddress((void**)&pmods, g_mods);
    cudaGetSymbolAddress((void**)&pmean, g_mean);
    cudaGetSymbolAddress((void**)&pqin,  g_qin);
    cudaGetSymbolAddress((void**)&px,    g_x);
    cudaGetSymbolAddress((void**)&ph,    g_h);
    cudaGetSymbolAddress((void**)&pw,    g_w);
    cudaGetSymbolAddress((void**)&pq,    g_q);
    cudaGetSymbolAddress((void**)&pK,    g_K);
    cudaGetSymbolAddress((void**)&pV,    g_V);
    cudaGetSymbolAddress((void**)&py,    g_y);

    __half* Wgt = pw;
    __half* Wqt = pw + (size_t)WSZ;
    __half* Wkt = pw + (size_t)2 * WSZ;
    __half* Wvt = pw + (size_t)3 * WSZ;
    __half* W1t = pw + (size_t)4 * WSZ;            // [4096,1024]
    __half* W2t = W1t + (size_t)DIM * FFN;         // [1024,4096]

    cudaFuncSetAttribute(gemm_fp16<2, __half>, cudaFuncAttributeMaxDynamicSharedMemorySize, GSMEM);
    cudaFuncSetAttribute(gemm_fp16<3, __half>, cudaFuncAttributeMaxDynamicSharedMemorySize, GSMEM);
    cudaFuncSetAttribute(gemm_fp16_sm<0, __half>, cudaFuncAttributeMaxDynamicSharedMemorySize, SGSMEM);
    cudaFuncSetAttribute(gemm_fp16_sm<1, __half>, cudaFuncAttributeMaxDynamicSharedMemorySize, SGSMEM);
    cudaFuncSetAttribute(gemm_fp16_sm<0, float>,  cudaFuncAttributeMaxDynamicSharedMemorySize, SGSMEM);

    dim3 tb(32, 8);
    transpose4_half_k<<<dim3(32, 32, 4), tb>>>(Wg, Wq, Wk, Wv, Wgt, Wqt, Wkt, Wvt);
    transpose_half_k<<<dim3(128, 32), tb>>>(W1, W1t, DIM, FFN);   // -> [4096][1024]
    transpose_half_k<<<dim3(32, 128), tb>>>(W2, W2t, FFN, DIM);   // -> [1024][4096]

    prep_mods_k<<<8192, 256>>>((const float4*)m0, (const float4*)m1, (const float4*)m2,
                               (__half2*)pmods, (__half2*)(pmods + BD),
                               (__half2*)(pmods + 2 * BD), (__half2*)pmean, (int)(BD / 4));

    dim3 gSm(DIM / BN, BB / SBM, 1);   // 8 x 256 = 2048 CTAs (small-tile)
    dim3 gF(FFN / BN, BB / BM, 1);     // 32 x 128
    dim3 gKV6(DIM / BN, BB / BM, 6);   // merged K+V batch

    // qin = half( domain + mean@Wg + bg )   [small tile]
    gemm_fp16_sm<1, __half><<<gSm, NTHR, SGSMEM>>>(pmean, Wgt, bg, dom, pqin, DIM, DIM);
    // K_j = half(m_j@Wk + bk); V_j = half(m_j@Wv + bv)   [merged z=6, big tile]
    gemm_fp16<3, __half><<<gKV6, NTHR, GSMEM>>>(pmods, nullptr, nullptr, Wkt, Wvt, bk, bv,
                                                nullptr, pK, pV, nullptr, DIM, DIM);
    // q = half(qin@Wq + bq)   [small tile]
    gemm_fp16_sm<0, __half><<<gSm, NTHR, SGSMEM>>>(pqin, Wqt, bq, nullptr, pq, DIM, DIM);

    attn_ln1_k<<<BB, 512>>>(pq, pK, pK + BD, pK + 2 * BD,
                            pV, pV + BD, pV + 2 * BD,
                            dom, g1, be1, px);

    // h = half(relu(x@W1 + b1))   [big tile]
    gemm_fp16<2, __half><<<gF, NTHR, GSMEM>>>(px, px, px, W1t, nullptr, b1, nullptr,
                                              nullptr, ph, ph, ph, DIM, FFN);
    // y = h@W2 + b2  (fp32 out)   [small tile]
    gemm_fp16_sm<0, float><<<gSm, NTHR, SGSMEM>>>(ph, W2t, b2, nullptr, py, FFN, DIM);

    final_k<<<BB, 256>>>(px, py, g2, be2, Ww, bw, out);
}

// round 16
// speedup vs baseline: 1.0383x; 1.0383x over previous
#include <cuda_runtime.h>
#include <cuda_fp16.h>
#include <math.h>
#include <stdint.h>

// ---------------- problem constants ----------------
#define BB   16384
#define DIM  1024
#define HH   16
#define HD   64
#define FFN  4096
#define LNEPS 1e-5f

#define BD   ((size_t)BB * DIM)
#define BF   ((size_t)BB * FFN)
#define WSZ  (1024*1024)

// ---------------- scratch ----------------
__device__ __half g_mods[3 * BD];
__device__ __half g_mean[BD];
__device__ __half g_qin [BD];
__device__ __half g_x   [BD];
__device__ __half g_h   [BF];
__device__ __half g_q   [BD];
__device__ __half g_K   [3 * BD];
__device__ __half g_V   [3 * BD];
__device__ __half g_w   [4 * WSZ + 2 * (size_t)DIM * FFN];
__device__ float  g_y   [BD];

// ---------------- prep kernels ----------------
__global__ void prep_mods_k(const float4* __restrict__ a, const float4* __restrict__ b,
                            const float4* __restrict__ c,
                            __half2* __restrict__ o0, __half2* __restrict__ o1,
                            __half2* __restrict__ o2, __half2* __restrict__ om, int n4) {
    int i = blockIdx.x * blockDim.x + threadIdx.x;
    int st = gridDim.x * blockDim.x;
    const float third = 1.f / 3.f;
    for (; i < n4; i += st) {
        float4 x = a[i], y = b[i], z = c[i];
        o0[2*i]   = __floats2half2_rn(x.x, x.y);
        o0[2*i+1] = __floats2half2_rn(x.z, x.w);
        o1[2*i]   = __floats2half2_rn(y.x, y.y);
        o1[2*i+1] = __floats2half2_rn(y.z, y.w);
        o2[2*i]   = __floats2half2_rn(z.x, z.y);
        o2[2*i+1] = __floats2half2_rn(z.z, z.w);
        om[2*i]   = __floats2half2_rn((x.x + y.x + z.x) * third, (x.y + y.y + z.y) * third);
        om[2*i+1] = __floats2half2_rn((x.z + y.z + z.z) * third, (x.w + y.w + z.w) * third);
    }
}
// Batched transpose: z selects among up to 4 DIMxDIM weights.
__global__ void transpose4_half_k(const float* __restrict__ Wa, const float* __restrict__ Wb,
                                  const float* __restrict__ Wc, const float* __restrict__ Wd,
                                  __half* __restrict__ Ta, __half* __restrict__ Tb,
                                  __half* __restrict__ Tc, __half* __restrict__ Td) {
    __shared__ float t[32][33];
    const float* W = (blockIdx.z == 0) ? Wa : (blockIdx.z == 1) ? Wb
                   : (blockIdx.z == 2) ? Wc : Wd;
    __half* Wt = (blockIdx.z == 0) ? Ta : (blockIdx.z == 1) ? Tb
               : (blockIdx.z == 2) ? Tc : Td;
    int nb = blockIdx.x * 32, kb = blockIdx.y * 32;
    int tx = threadIdx.x, ty = threadIdx.y;
    #pragma unroll
    for (int r = 0; r < 32; r += 8)
        t[ty + r][tx] = W[(size_t)(kb + ty + r) * DIM + nb + tx];
    __syncthreads();
    #pragma unroll
    for (int r = 0; r < 32; r += 8)
        Wt[(size_t)(nb + ty + r) * DIM + kb + tx] = __float2half(t[tx][ty + r]);
}
// Generic single transpose (for W1, W2)
__global__ void transpose_half_k(const float* __restrict__ W, __half* __restrict__ Wt,
                                 int K, int N) {
    __shared__ float t[32][33];
    int nb = blockIdx.x * 32, kb = blockIdx.y * 32;
    int tx = threadIdx.x, ty = threadIdx.y;
    #pragma unroll
    for (int r = 0; r < 32; r += 8)
        t[ty + r][tx] = W[(size_t)(kb + ty + r) * N + nb + tx];
    __syncthreads();
    #pragma unroll
    for (int r = 0; r < 32; r += 8)
        Wt[(size_t)(nb + ty + r) * K + kb + tx] = __float2half(t[tx][ty + r]);
}

// ---------------- fp16 mma.sync GEMM: 128x128x64, 4 warps, warp tile 64x64 ------
#define BM 128
#define BN 128
#define BK 64
#define NSTG 3
#define NTHR 128
#define ASTR 72                      // halves per row (64 + 8 pad; conflict-free LDSM)
#define BSTR 72
#define A_ELEMS (BM * ASTR)          // 9216 halves / stage
#define B_ELEMS (BN * BSTR)
#define GSMEM (NSTG * (A_ELEMS + B_ELEMS) * 2)   // 110592 bytes -> 2 CTA/SM

__device__ __forceinline__ void ldsm4(uint32_t* r, uint32_t addr) {
    asm volatile("ldmatrix.sync.aligned.m8n8.x4.shared.b16 {%0,%1,%2,%3}, [%4];"
                 : "=r"(r[0]), "=r"(r[1]), "=r"(r[2]), "=r"(r[3]) : "r"(addr));
}

// MODE: 0 = +bias; 2 = relu(+bias);
// MODE 5 = merged K/V/qin batch, z in [0,7):
//   z<3 : K_j  = mods_j @ WtK  + bK          -> C0 + z*BD
//   3<=z<6: V_j = mods_j @ WtV + bV          -> C1 + (z-3)*BD
//   z==6: qin = mean @ WtG + bG + dom(addsrc) -> C2
template <int MODE, typename OutT>
__global__ __launch_bounds__(NTHR, 2) void gemm_fp16(
    const __half* __restrict__ A0, const __half* __restrict__ Amean,
    const __half* __restrict__ WtK, const __half* __restrict__ WtV,
    const __half* __restrict__ WtG,
    const float* __restrict__ bK, const float* __restrict__ bV,
    const float* __restrict__ bG, const float* __restrict__ addsrc,
    OutT* __restrict__ C0, OutT* __restrict__ C1, OutT* __restrict__ C2,
    int K, int Nc)
{
    extern __shared__ __align__(16) __half smh[];
    __half* As = smh;
    __half* Bs = smh + NSTG * A_ELEMS;

    const __half* A;
    const __half* W;
    const float*  bvec;
    OutT*         C;
    bool          doadd = false;
    if (MODE == 5) {
        int z = blockIdx.z;
        if (z < 3) {
            A = A0 + (size_t)z * BD;       W = WtK; bvec = bK; C = C0 + (size_t)z * BD;
        } else if (z < 6) {
            A = A0 + (size_t)(z - 3) * BD; W = WtV; bvec = bV; C = C1 + (size_t)(z - 3) * BD;
        } else {
            A = Amean; W = WtG; bvec = bG; C = C2; doadd = true;
        }
    } else {
        A = A0; W = WtK; bvec = bK; C = C0;
    }

    const int m0 = blockIdx.y * BM, n0 = blockIdx.x * BN;
    const int tid  = threadIdx.x;
    const int lane = tid & 31, warp = tid >> 5;
    const int wm = warp & 1, wn = warp >> 1;          // 2m x 2n, warp tile 64x64
    const int g = lane >> 2, tig = lane & 3;

    const uint32_t sm_a = (uint32_t)__cvta_generic_to_shared(As);
    const uint32_t sm_b = (uint32_t)__cvta_generic_to_shared(Bs);

    const int a_off = (wm * 64 + (lane & 15)) * ASTR + (lane >> 4) * 8;
    const int b_off = (wn * 64 + (lane & 7) + ((lane >= 16) ? 8 : 0)) * BSTR
                    + ((lane >> 3) & 1) * 8;

    auto load_stage = [&](int stage, int kb) {
        const __half* Ag = A + (size_t)m0 * K + kb;
        #pragma unroll
        for (int p = 0; p < 8; p++) {                 // 128 rows x 8 segs = 1024 chunks
            int cidx = tid + p * NTHR;
            int m = cidx >> 3, sg = cidx & 7;
            uint32_t dst = sm_a + (uint32_t)(stage * A_ELEMS + m * ASTR + sg * 8) * 2;
            const __half* src = Ag + (size_t)m * K + sg * 8;
            asm volatile("cp.async.cg.shared.global [%0], [%1], 16;\n" :: "r"(dst), "l"(src));
        }
        const __half* Bg = W + (size_t)n0 * K + kb;
        #pragma unroll
        for (int p = 0; p < 8; p++) {
            int cidx = tid + p * NTHR;
            int n = cidx >> 3, sg = cidx & 7;
            uint32_t dst = sm_b + (uint32_t)(stage * B_ELEMS + n * BSTR + sg * 8) * 2;
            const __half* src = Bg + (size_t)n * K + sg * 8;
            asm volatile("cp.async.cg.shared.global [%0], [%1], 16;\n" :: "r"(dst), "l"(src));
        }
        asm volatile("cp.async.commit_group;\n");
    };

    float c[4][8][4];
    #pragma unroll
    for (int i = 0; i < 4; i++)
        #pragma unroll
        for (int j = 0; j < 8; j++)
            #pragma unroll
            for (int l = 0; l < 4; l++) c[i][j][l] = 0.f;

    load_stage(0, 0);
    load_stage(1, BK);

    uint32_t af[2][4][4], bf[2][8][2];

    const int KT = K / BK;
    for (int kt = 0; kt < KT; ++kt) {
        if (kt + 1 < KT) asm volatile("cp.async.wait_group 1;\n");
        else             asm volatile("cp.async.wait_group 0;\n");
        __syncthreads();

        if (kt + 2 < KT) load_stage((kt + 2) % NSTG, (kt + 2) * BK);

        const int cur = kt % NSTG;
        const uint32_t abase = sm_a + (uint32_t)(cur * A_ELEMS + a_off) * 2;
        const uint32_t bbase = sm_b + (uint32_t)(cur * B_ELEMS + b_off) * 2;

        #pragma unroll
        for (int mi = 0; mi < 4; mi++)
            ldsm4(af[0][mi], abase + (uint32_t)(mi * 16 * ASTR) * 2);
        #pragma unroll
        for (int nip = 0; nip < 4; nip++) {
            uint32_t r[4];
            ldsm4(r, bbase + (uint32_t)(nip * 16 * BSTR) * 2);
            bf[0][2 * nip][0]     = r[0];
            bf[0][2 * nip][1]     = r[1];
            bf[0][2 * nip + 1][0] = r[2];
            bf[0][2 * nip + 1][1] = r[3];
        }

        #pragma unroll
        for (int ks = 0; ks < 4; ++ks) {
            const int cb = ks & 1;
            if (ks < 3) {
                const int nb = cb ^ 1;
                const int kk = (ks + 1) * 16;
                #pragma unroll
                for (int mi = 0; mi < 4; mi++)
                    ldsm4(af[nb][mi], abase + (uint32_t)(mi * 16 * ASTR + kk) * 2);
                #pragma unroll
                for (int nip = 0; nip < 4; nip++) {
                    uint32_t r[4];
                    ldsm4(r, bbase + (uint32_t)(nip * 16 * BSTR + kk) * 2);
                    bf[nb][2 * nip][0]     = r[0];
                    bf[nb][2 * nip][1]     = r[1];
                    bf[nb][2 * nip + 1][0] = r[2];
                    bf[nb][2 * nip + 1][1] = r[3];
                }
            }
            #pragma unroll
            for (int mi = 0; mi < 4; mi++)
                #pragma unroll
                for (int ni = 0; ni < 8; ni++) {
                    float* cc = c[mi][ni];
                    asm volatile(
                        "mma.sync.aligned.m16n8k16.row.col.f32.f16.f16.f32 "
                        "{%0,%1,%2,%3},{%4,%5,%6,%7},{%8,%9},{%0,%1,%2,%3};\n"
                        : "+f"(cc[0]), "+f"(cc[1]), "+f"(cc[2]), "+f"(cc[3])
                        : "r"(af[cb][mi][0]), "r"(af[cb][mi][1]),
                          "r"(af[cb][mi][2]), "r"(af[cb][mi][3]),
                          "r"(bf[cb][ni][0]), "r"(bf[cb][ni][1]));
                }
        }
    }

    // epilogue
    #pragma unroll
    for (int mi = 0; mi < 4; mi++) {
        int row = m0 + wm * 64 + mi * 16 + g;
        #pragma unroll
        for (int ni = 0; ni < 8; ni++) {
            int col = n0 + wn * 64 + ni * 8 + tig * 2;
            float bv0 = bvec[col], bv1 = bvec[col + 1];
            float v0 = c[mi][ni][0] + bv0, v1 = c[mi][ni][1] + bv1;
            float v2 = c[mi][ni][2] + bv0, v3 = c[mi][ni][3] + bv1;
            size_t i0 = (size_t)row * Nc + col;
            size_t i1 = (size_t)(row + 8) * Nc + col;
            if (MODE == 5) {
                if (doadd) {
                    v0 += addsrc[i0]; v1 += addsrc[i0 + 1];
                    v2 += addsrc[i1]; v3 += addsrc[i1 + 1];
                }
            } else if (MODE == 2) {
                v0 = fmaxf(v0, 0.f); v1 = fmaxf(v1, 0.f);
                v2 = fmaxf(v2, 0.f); v3 = fmaxf(v3, 0.f);
            }
            if (sizeof(OutT) == 2) {
                *(__half2*)&((__half*)C)[i0] = __floats2half2_rn(v0, v1);
                *(__half2*)&((__half*)C)[i1] = __floats2half2_rn(v2, v3);
            } else {
                *(float2*)&((float*)C)[i0] = make_float2(v0, v1);
                *(float2*)&((float*)C)[i1] = make_float2(v2, v3);
            }
        }
    }
}

// ---------------- attention (3 keys) + residual + LN1, fp16 q/K/V ----------------
__global__ __launch_bounds__(512) void attn_ln1_k(
    const __half* __restrict__ q,
    const __half* __restrict__ K0, const __half* __restrict__ K1, const __half* __restrict__ K2,
    const __half* __restrict__ V0, const __half* __restrict__ V1, const __half* __restrict__ V2,
    const float* __restrict__ dom, const float* __restrict__ gam, const float* __restrict__ bet,
    __half* __restrict__ xo)
{
    __shared__ float sout[DIM];
    __shared__ float rS[16], rQ[16], stats[2];
    const int b = blockIdx.x, tid = threadIdx.x;
    const int h = tid >> 5, lane = tid & 31;
    const size_t rowb = (size_t)b * DIM;
    const size_t off = rowb + h * HD + lane * 2;

    float2 qv = __half22float2(*(const __half2*)(q + off));
    float2 k0 = __half22float2(*(const __half2*)(K0 + off));
    float2 k1 = __half22float2(*(const __half2*)(K1 + off));
    float2 k2 = __half22float2(*(const __half2*)(K2 + off));
    float d0 = qv.x * k0.x + qv.y * k0.y;
    float d1 = qv.x * k1.x + qv.y * k1.y;
    float d2 = qv.x * k2.x + qv.y * k2.y;
    #pragma unroll
    for (int o = 16; o; o >>= 1) {
        d0 += __shfl_xor_sync(0xffffffffu, d0, o);
        d1 += __shfl_xor_sync(0xffffffffu, d1, o);
        d2 += __shfl_xor_sync(0xffffffffu, d2, o);
    }
    float s0 = d0 * 0.125f, s1 = d1 * 0.125f, s2 = d2 * 0.125f;
    float mx = fmaxf(s0, fmaxf(s1, s2));
    float e0 = expf(s0 - mx), e1 = expf(s1 - mx), e2 = expf(s2 - mx);
    float inv = 1.f / (e0 + e1 + e2);
    float p0 = e0 * inv, p1 = e1 * inv, p2 = e2 * inv;

    float2 v0 = __half22float2(*(const __half2*)(V0 + off));
    float2 v1 = __half22float2(*(const __half2*)(V1 + off));
    float2 v2 = __half22float2(*(const __half2*)(V2 + off));
    float ox = p0 * v0.x + p1 * v1.x + p2 * v2.x;
    float oy = p0 * v0.y + p1 * v1.y + p2 * v2.y;
    int dloc = h * HD + lane * 2;
    sout[dloc] = ox;
    sout[dloc + 1] = oy;
    __syncthreads();

    int d0i = tid * 2;
    float t0 = dom[rowb + d0i]     + sout[d0i];
    float t1 = dom[rowb + d0i + 1] + sout[d0i + 1];
    float s = t0 + t1, sq = t0 * t0 + t1 * t1;
    #pragma unroll
    for (int o = 16; o; o >>= 1) {
        s  += __shfl_xor_sync(0xffffffffu, s, o);
        sq += __shfl_xor_sync(0xffffffffu, sq, o);
    }
    if (lane == 0) { rS[h] = s; rQ[h] = sq; }
    __syncthreads();
    if (tid == 0) {
        float S = 0.f, Q = 0.f;
        #pragma unroll
        for (int i = 0; i < 16; i++) { S += rS[i]; Q += rQ[i]; }
        float mu = S * (1.f / DIM);
        float var = Q * (1.f / DIM) - mu * mu;
        stats[0] = mu;
        stats[1] = rsqrtf(var + LNEPS);
    }
    __syncthreads();
    float mu = stats[0], r = stats[1];
    float x0 = (t0 - mu) * r * gam[d0i]     + bet[d0i];
    float x1 = (t1 - mu) * r * gam[d0i + 1] + bet[d0i + 1];
    *(__half2*)(xo + rowb + d0i) = __floats2half2_rn(x0, x1);
}

// ---------------- residual + LN2 + [DIM,3] matvec + softmax ----------------
__global__ __launch_bounds__(256) void final_k(
    const __half* __restrict__ x, const float* __restrict__ y,
    const float* __restrict__ g2, const float* __restrict__ b2,
    const float* __restrict__ Ww, const float* __restrict__ bw,
    float* __restrict__ out)
{
    __shared__ float rs[8], rq[8], rl[8][3], stats[2];
    const int b = blockIdx.x, tid = threadIdx.x;
    const int lane = tid & 31, w = tid >> 5;
    const size_t base = (size_t)b * DIM;

    float t[4];
    float s = 0.f, sq = 0.f;
    #pragma unroll
    for (int i = 0; i < 4; i++) {
        int d = tid + i * 256;
        float v = __half2float(x[base + d]) + y[base + d];
        t[i] = v; s += v; sq += v * v;
    }
    #pragma unroll
    for (int o = 16; o; o >>= 1) {
        s  += __shfl_xor_sync(0xffffffffu, s, o);
        sq += __shfl_xor_sync(0xffffffffu, sq, o);
    }
    if (lane == 0) { rs[w] = s; rq[w] = sq; }
    __syncthreads();
    if (tid == 0) {
        float S = 0.f, Q = 0.f;
        #pragma unroll
        for (int i = 0; i < 8; i++) { S += rs[i]; Q += rq[i]; }
        float mu = S * (1.f / DIM);
        float var = Q * (1.f / DIM) - mu * mu;
        stats[0] = mu;
        stats[1] = rsqrtf(var + LNEPS);
    }
    __syncthreads();
    float mu = stats[0], r = stats[1];
    float l0 = 0.f, l1 = 0.f, l2 = 0.f;
    #pragma unroll
    for (int i = 0; i < 4; i++) {
        int d = tid + i * 256;
        float xn = (t[i] - mu) * r * g2[d] + b2[d];
        l0 += xn * Ww[d * 3];
        l1 += xn * Ww[d * 3 + 1];
        l2 += xn * Ww[d * 3 + 2];
    }
    #pragma unroll
    for (int o = 16; o; o >>= 1) {
        l0 += __shfl_xor_sync(0xffffffffu, l0, o);
        l1 += __shfl_xor_sync(0xffffffffu, l1, o);
        l2 += __shfl_xor_sync(0xffffffffu, l2, o);
    }
    if (lane == 0) { rl[w][0] = l0; rl[w][1] = l1; rl[w][2] = l2; }
    __syncthreads();
    if (tid == 0) {
        float a0 = bw[0], a1 = bw[1], a2 = bw[2];
        #pragma unroll
        for (int i = 0; i < 8; i++) { a0 += rl[i][0]; a1 += rl[i][1]; a2 += rl[i][2]; }
        float m = fmaxf(a0, fmaxf(a1, a2));
        float e0 = expf(a0 - m), e1 = expf(a1 - m), e2 = expf(a2 - m);
        float inv = 1.f / (e0 + e1 + e2);
        out[(size_t)b * 3]     = e0 * inv;
        out[(size_t)b * 3 + 1] = e1 * inv;
        out[(size_t)b * 3 + 2] = e2 * inv;
    }
}

// ---------------- host launcher ----------------
extern "C" void kernel_launch(void* const* d_in, const int* in_sizes, int n_in,
                              void* d_out, int out_size)
{
    (void)in_sizes; (void)n_in; (void)out_size;
    const float* m0  = (const float*)d_in[0];
    const float* m1  = (const float*)d_in[1];
    const float* m2  = (const float*)d_in[2];
    const float* dom = (const float*)d_in[3];
    const float* Wg  = (const float*)d_in[4];
    const float* bg  = (const float*)d_in[5];
    const float* Wq  = (const float*)d_in[6];
    const float* bq  = (const float*)d_in[7];
    const float* Wk  = (const float*)d_in[8];
    const float* bk  = (const float*)d_in[9];
    const float* Wv  = (const float*)d_in[10];
    const float* bv  = (const float*)d_in[11];
    const float* W1  = (const float*)d_in[12];
    const float* b1  = (const float*)d_in[13];
    const float* W2  = (const float*)d_in[14];
    const float* b2  = (const float*)d_in[15];
    const float* g1  = (const float*)d_in[16];
    const float* be1 = (const float*)d_in[17];
    const float* g2  = (const float*)d_in[18];
    const float* be2 = (const float*)d_in[19];
    const float* Ww  = (const float*)d_in[20];
    const float* bw  = (const float*)d_in[21];
    float* out = (float*)d_out;

    __half *pmods, *pmean, *pqin, *px, *ph, *pw, *pq, *pK, *pV;
    float  *py;
    cudaGetSymbolAddress((void**)&pmods, g_mods);
    cudaGetSymbolAddress((void**)&pmean, g_mean);
    cudaGetSymbolAddress((void**)&pqin,  g_qin);
    cudaGetSymbolAddress((void**)&px,    g_x);
    cudaGetSymbolAddress((void**)&ph,    g_h);
    cudaGetSymbolAddress((void**)&pw,    g_w);
    cudaGetSymbolAddress((void**)&pq,    g_q);
    cudaGetSymbolAddress((void**)&pK,    g_K);
    cudaGetSymbolAddress((void**)&pV,    g_V);
    cudaGetSymbolAddress((void**)&py,    g_y);

    __half* Wgt = pw;
    __half* Wqt = pw + (size_t)WSZ;
    __half* Wkt = pw + (size_t)2 * WSZ;
    __half* Wvt = pw + (size_t)3 * WSZ;
    __half* W1t = pw + (size_t)4 * WSZ;            // [4096,1024]
    __half* W2t = W1t + (size_t)DIM * FFN;         // [1024,4096]

    cudaFuncSetAttribute(gemm_fp16<0, __half>, cudaFuncAttributeMaxDynamicSharedMemorySize, GSMEM);
    cudaFuncSetAttribute(gemm_fp16<2, __half>, cudaFuncAttributeMaxDynamicSharedMemorySize, GSMEM);
    cudaFuncSetAttribute(gemm_fp16<5, __half>, cudaFuncAttributeMaxDynamicSharedMemorySize, GSMEM);
    cudaFuncSetAttribute(gemm_fp16<0, float>,  cudaFuncAttributeMaxDynamicSharedMemorySize, GSMEM);

    dim3 tb(32, 8);
    transpose4_half_k<<<dim3(32, 32, 4), tb>>>(Wg, Wq, Wk, Wv, Wgt, Wqt, Wkt, Wvt);
    transpose_half_k<<<dim3(128, 32), tb>>>(W1, W1t, DIM, FFN);   // -> [4096][1024]
    transpose_half_k<<<dim3(32, 128), tb>>>(W2, W2t, FFN, DIM);   // -> [1024][4096]

    prep_mods_k<<<8192, 256>>>((const float4*)m0, (const float4*)m1, (const float4*)m2,
                               (__half2*)pmods, (__half2*)(pmods + BD),
                               (__half2*)(pmods + 2 * BD), (__half2*)pmean, (int)(BD / 4));

    dim3 gD(DIM / BN, BB / BM, 1);     // 8 x 128
    dim3 gF(FFN / BN, BB / BM, 1);     // 32 x 128
    dim3 gKVQ(DIM / BN, BB / BM, 7);   // merged K+V+qin batch, 7168 CTAs

    // merged: K_j, V_j, and qin = half(dom + mean@Wg + bg)
    gemm_fp16<5, __half><<<gKVQ, NTHR, GSMEM>>>(
        pmods, pmean, Wkt, Wvt, Wgt, bk, bv, bg, dom,
        pK, pV, pqin, DIM, DIM);
    // q = half(qin@Wq + bq)
    gemm_fp16<0, __half><<<gD, NTHR, GSMEM>>>(
        pqin, nullptr, Wqt, nullptr, nullptr, bq, nullptr, nullptr, nullptr,
        pq, nullptr, nullptr, DIM, DIM);

    attn_ln1_k<<<BB, 512>>>(pq, pK, pK + BD, pK + 2 * BD,
                            pV, pV + BD, pV + 2 * BD,
                            dom, g1, be1, px);

    // h = half(relu(x@W1 + b1))
    gemm_fp16<2, __half><<<gF, NTHR, GSMEM>>>(
        px, nullptr, W1t, nullptr, nullptr, b1, nullptr, nullptr, nullptr,
        ph, nullptr, nullptr, DIM, FFN);
    // y = h@W2 + b2  (fp32 out)
    gemm_fp16<0, float><<<gD, NTHR, GSMEM>>>(
        ph, nullptr, W2t, nullptr, nullptr, b2, nullptr, nullptr, nullptr,
        py, nullptr, nullptr, FFN, DIM);

    final_k<<<BB, 256>>>(px, py, g2, be2, Ww, bw, out);
}